// round 1
// baseline (speedup 1.0000x reference)
#include <cuda_runtime.h>
#include <cuda_bf16.h>

// Problem constants (B=4, Q=256, K=1024, H=128)
#define BB 4
#define QQ 256
#define KK 1024
#define HH 128
#define TILE 64           // k-rows per shared tile
#define PITCH 132         // padded row pitch in floats (conflict-free LDS.128)

// Scratch for projections (device globals — no allocation allowed)
__device__ float g_qp[BB * QQ * HH];   // 512 KB
__device__ float g_kp[BB * KK * HH];   // 2 MB

__device__ __forceinline__ float fast_tanh(float x) {
    float y;
    asm("tanh.approx.f32 %0, %1;" : "=f"(y) : "f"(x));
    return y;
}

// out[row][h] = sum_d in[row][d] * W[h][d]   (torch Linear: x @ W.T)
// which == 0 -> g_qp, which == 1 -> g_kp
__global__ __launch_bounds__(HH) void proj_kernel(const float* __restrict__ in,
                                                  const float* __restrict__ W,
                                                  int which) {
    __shared__ float s_in[HH];
    int row = blockIdx.x;
    int h = threadIdx.x;
    s_in[h] = in[row * HH + h];
    __syncthreads();

    const float4* w4 = (const float4*)(W + h * HH);
    const float4* s4 = (const float4*)s_in;
    float acc = 0.f;
#pragma unroll
    for (int i = 0; i < HH / 4; ++i) {
        float4 a = w4[i];
        float4 b = s4[i];
        acc += a.x * b.x + a.y * b.y + a.z * b.z + a.w * b.w;
    }
    float* out = which ? g_kp : g_qp;
    out[row * HH + h] = acc;
}

// One block per (b, q). 128 threads.
__global__ __launch_bounds__(128) void attn_kernel(const float* __restrict__ value,
                                                   const int* __restrict__ mask,
                                                   const float* __restrict__ vvec,
                                                   float* __restrict__ out_aw,
                                                   float* __restrict__ out_ctx) {
    __shared__ float s_qp[HH];
    __shared__ float s_v[HH];
    __shared__ float s_scores[KK];
    __shared__ float s_part[128];
    __shared__ float s_tile[TILE * PITCH];
    __shared__ float s_red[4];

    const int tid = threadIdx.x;
    const int bq = blockIdx.x;         // b*QQ + q
    const int b = bq >> 8;

    s_qp[tid] = g_qp[bq * HH + tid];
    s_v[tid]  = vvec[tid];
    __syncthreads();

    const float* kp_b = g_kp + (size_t)b * KK * HH;
    const int* mrow = mask + (size_t)bq * KK;

    const int krow = tid & (TILE - 1);          // 0..63 : k row within tile
    const int hh0 = (tid >> 6) * (HH / 8);      // float4 start: 0 or 16 (h half)
    const float4* qp4 = (const float4*)s_qp;
    const float4* vp4 = (const float4*)s_v;

    // ---- score phase: 16 tiles of 64 k-rows ----
    for (int t = 0; t < KK / TILE; ++t) {
        // stage tile: TILE*HH floats = 2048 float4; 128 threads -> 16 each
        const float4* src = (const float4*)(kp_b + t * TILE * HH);
#pragma unroll
        for (int i = 0; i < 16; ++i) {
            int idx = tid + i * 128;            // 0..2047
            int row = idx >> 5;                 // 32 float4 per row
            int col = idx & 31;
            ((float4*)s_tile)[row * (PITCH / 4) + col] = src[idx];
        }
        __syncthreads();

        const float4* kr = (const float4*)s_tile + krow * (PITCH / 4) + hh0;
        float acc = 0.f;
#pragma unroll
        for (int i = 0; i < HH / 8; ++i) {      // 16 float4 = 64 h values (half of H)
            float4 kp = kr[i];
            float4 qq = qp4[hh0 + i];
            float4 vv = vp4[hh0 + i];
            acc += vv.x * fast_tanh(qq.x + kp.x);
            acc += vv.y * fast_tanh(qq.y + kp.y);
            acc += vv.z * fast_tanh(qq.z + kp.z);
            acc += vv.w * fast_tanh(qq.w + kp.w);
        }
        s_part[tid] = acc;
        __syncthreads();
        if (tid < TILE) {
            int k = t * TILE + tid;
            float m = (float)mrow[k];
            // faithful to source: NEG_MASK_SCALE = -1e-09
            s_scores[k] = s_part[tid] + s_part[tid + TILE] + (-1e-9f) * (1.0f - m);
        }
        __syncthreads();
    }

    // ---- softmax over K=1024 ----
    float lmax = -1e30f;
    for (int i = tid; i < KK; i += 128) lmax = fmaxf(lmax, s_scores[i]);
#pragma unroll
    for (int o = 16; o; o >>= 1) lmax = fmaxf(lmax, __shfl_xor_sync(~0u, lmax, o));
    if ((tid & 31) == 0) s_red[tid >> 5] = lmax;
    __syncthreads();
    float gmax = fmaxf(fmaxf(s_red[0], s_red[1]), fmaxf(s_red[2], s_red[3]));

    float lsum = 0.f;
    for (int i = tid; i < KK; i += 128) {
        float e = __expf(s_scores[i] - gmax);
        s_scores[i] = e;
        lsum += e;
    }
#pragma unroll
    for (int o = 16; o; o >>= 1) lsum += __shfl_xor_sync(~0u, lsum, o);
    __syncthreads();                     // protect s_red reuse
    if ((tid & 31) == 0) s_red[tid >> 5] = lsum;
    __syncthreads();
    float inv = 1.0f / (s_red[0] + s_red[1] + s_red[2] + s_red[3]);

    float* aw = out_aw + (size_t)bq * KK;
    for (int i = tid; i < KK; i += 128) {
        float w = s_scores[i] * inv;
        s_scores[i] = w;
        aw[i] = w;
    }
    __syncthreads();

    // ---- context: ctx[h] = sum_k w[k] * value[b][k][h] ----
    const float* vb = value + (size_t)b * KK * HH + tid;
    float a0 = 0.f, a1 = 0.f, a2 = 0.f, a3 = 0.f;
#pragma unroll 4
    for (int k = 0; k < KK; k += 4) {
        a0 += s_scores[k + 0] * vb[(k + 0) * HH];
        a1 += s_scores[k + 1] * vb[(k + 1) * HH];
        a2 += s_scores[k + 2] * vb[(k + 2) * HH];
        a3 += s_scores[k + 3] * vb[(k + 3) * HH];
    }
    out_ctx[(size_t)bq * HH + tid] = (a0 + a1) + (a2 + a3);
}

extern "C" void kernel_launch(void* const* d_in, const int* in_sizes, int n_in,
                              void* d_out, int out_size) {
    // metadata order: query, key, value, mask, Wq, Wk, v
    const float* query = (const float*)d_in[0];
    const float* key   = (const float*)d_in[1];
    const float* value = (const float*)d_in[2];
    const int*   mask  = (const int*)d_in[3];
    const float* Wq    = (const float*)d_in[4];
    const float* Wk    = (const float*)d_in[5];
    const float* vvec  = (const float*)d_in[6];

    float* out_aw  = (float*)d_out;                          // (B,Q,K)
    float* out_ctx = out_aw + (size_t)BB * QQ * KK;          // (B,Q,H)

    proj_kernel<<<BB * QQ, HH>>>(query, Wq, 0);
    proj_kernel<<<BB * KK, HH>>>(key, Wk, 1);
    attn_kernel<<<BB * QQ, 128>>>(value, mask, vvec, out_aw, out_ctx);
}

// round 3
// speedup vs baseline: 1.9951x; 1.9951x over previous
#include <cuda_runtime.h>
#include <cuda_bf16.h>
#include <cstdint>

// Problem constants (B=4, Q=256, K=1024, H=128)
#define BB 4
#define QQ 256
#define KK 1024
#define HH 128
#define QT 8            // queries per block
#define TILE 64         // k-rows per shared tile
#define P4 33           // float4 pitch of kp tile row (132 floats)

// Scratch for projections (device globals — no allocation allowed)
__device__ float g_qp[BB * QQ * HH];   // 512 KB
__device__ float g_kp[BB * KK * HH];   // 2 MB

__device__ __forceinline__ float fast_tanh(float x) {
    float y;
    asm("tanh.approx.f32 %0, %1;" : "=f"(y) : "f"(x));
    return y;
}

__device__ __forceinline__ void cp_async16(void* dst, const void* src) {
    uint32_t d = (uint32_t)__cvta_generic_to_shared(dst);
    asm volatile("cp.async.ca.shared.global [%0], [%1], 16;\n" :: "r"(d), "l"(src));
}

// ---------------- Fused projection GEMM: out[row][h] = sum_d in[row][d] * W[h][d]
// 64x64 tile per block, 256 threads (16x16), 4x4 register tile (stride-16 spread).
// blocks 0..31  : q-proj (1024 rows), blocks 32..159 : k-proj (4096 rows)
__global__ __launch_bounds__(256) void proj_kernel(
    const float* __restrict__ query, const float* __restrict__ key,
    const float* __restrict__ Wq, const float* __restrict__ Wk) {
    __shared__ float s_a[64 * 36];   // in rows tile, 32-kk chunk, pitch 36 floats
    __shared__ float s_b[64 * 36];   // W rows tile

    int bx = blockIdx.x;
    const float* in; const float* W; float* out;
    int rowTile, hTile;
    if (bx < 32) { in = query; W = Wq; out = g_qp; rowTile = (bx >> 1) * 64; hTile = (bx & 1) * 64; }
    else { bx -= 32; in = key; W = Wk; out = g_kp; rowTile = (bx >> 1) * 64; hTile = (bx & 1) * 64; }

    const int tid = threadIdx.x;
    const int tx = tid & 15;
    const int ty = tid >> 4;

    float acc[4][4] = {};

    for (int kc = 0; kc < 4; ++kc) {
        __syncthreads();
        // stage 64x32 chunk of both operands (512 float4 each, 2 per thread each)
        {
            int idx = tid;
#pragma unroll
            for (int i = 0; i < 2; ++i, idx += 256) {
                int r = idx >> 3, c = idx & 7;
                float4 va = ((const float4*)(in + (size_t)(rowTile + r) * HH + kc * 32))[c];
                ((float4*)s_a)[r * 9 + c] = va;
                float4 vb = ((const float4*)(W + (size_t)(hTile + r) * HH + kc * 32))[c];
                ((float4*)s_b)[r * 9 + c] = vb;
            }
        }
        __syncthreads();

#pragma unroll
        for (int s = 0; s < 8; ++s) {
            float4 a[4], b[4];
#pragma unroll
            for (int i = 0; i < 4; ++i) a[i] = ((const float4*)s_a)[(ty + 16 * i) * 9 + s];
#pragma unroll
            for (int j = 0; j < 4; ++j) b[j] = ((const float4*)s_b)[(tx + 16 * j) * 9 + s];
#pragma unroll
            for (int i = 0; i < 4; ++i)
#pragma unroll
                for (int j = 0; j < 4; ++j)
                    acc[i][j] += a[i].x * b[j].x + a[i].y * b[j].y
                               + a[i].z * b[j].z + a[i].w * b[j].w;
        }
    }

#pragma unroll
    for (int i = 0; i < 4; ++i)
#pragma unroll
        for (int j = 0; j < 4; ++j)
            out[(size_t)(rowTile + ty + 16 * i) * HH + hTile + tx + 16 * j] = acc[i][j];
}

// ---------------- Fused attention: one block per (b, 8-query tile), 256 threads.
// Warp w owns query q0+w. Thread: hs = (lane>>3) h-slice of 32, ksub = lane&7.
__global__ __launch_bounds__(256) void attn_kernel(const float* __restrict__ value,
                                                   const int* __restrict__ mask,
                                                   const float* __restrict__ vvec,
                                                   float* __restrict__ out_aw,
                                                   float* __restrict__ out_ctx) {
    extern __shared__ float sm[];
    float4* s_kp = (float4*)sm;              // [2][TILE][P4] float4
    float*  s_sc = sm + 2 * TILE * P4 * 4;   // [QT][KK]

    const int tid = threadIdx.x;
    const int bx = blockIdx.x;
    const int b = bx >> 5;
    const int q0 = (bx & 31) * QT;
    const int warp = tid >> 5;               // == q within tile
    const int lane = tid & 31;
    const int hs = lane >> 3;
    const int ksub = lane & 7;

    const float4* kp4 = (const float4*)g_kp + (size_t)b * KK * (HH / 4);

    // per-thread register operands: q-projection slice and v slice (32 floats each)
    float4 qq[8], vv[8];
    {
        const float4* qp = (const float4*)g_qp + (size_t)(b * QQ + q0 + warp) * (HH / 4) + hs * 8;
        const float4* v4 = (const float4*)vvec + hs * 8;
#pragma unroll
        for (int i = 0; i < 8; ++i) { qq[i] = qp[i]; vv[i] = v4[i]; }
    }

    auto stage = [&](int t, int buf) {
        const float4* src = kp4 + (size_t)t * TILE * (HH / 4);
        float4* dst = s_kp + buf * (TILE * P4);
#pragma unroll
        for (int i = 0; i < 8; ++i) {
            int idx = tid + i * 256;              // 0..2047
            int r = idx >> 5, c = idx & 31;
            cp_async16(dst + r * P4 + c, src + idx);
        }
        asm volatile("cp.async.commit_group;\n");
    };

    stage(0, 0);
    for (int t = 0; t < KK / TILE; ++t) {
        const int buf = t & 1;
        if (t < KK / TILE - 1) {
            stage(t + 1, buf ^ 1);
            asm volatile("cp.async.wait_group 1;\n");
        } else {
            asm volatile("cp.async.wait_group 0;\n");
        }
        __syncthreads();

        const float4* base = s_kp + buf * (TILE * P4) + hs * 8;
#pragma unroll
        for (int it = 0; it < 8; ++it) {
            const int kk = ksub + it * 8;
            const float4* kr = base + kk * P4;
            float acc = 0.f;
#pragma unroll
            for (int i = 0; i < 8; ++i) {
                float4 kp = kr[i];
                acc += vv[i].x * fast_tanh(qq[i].x + kp.x);
                acc += vv[i].y * fast_tanh(qq[i].y + kp.y);
                acc += vv[i].z * fast_tanh(qq[i].z + kp.z);
                acc += vv[i].w * fast_tanh(qq[i].w + kp.w);
            }
            acc += __shfl_xor_sync(~0u, acc, 8);
            acc += __shfl_xor_sync(~0u, acc, 16);
            if (hs == 0) s_sc[warp * KK + t * TILE + kk] = acc;
        }
        __syncthreads();   // buffer `buf` is restaged next iteration
    }

    // ---- softmax: warp `warp` handles its own query row (32 elems/lane in regs)
    {
        float* sc = s_sc + warp * KK;
        const int* mrow = mask + (size_t)(b * QQ + q0 + warp) * KK;
        float vals[32];
        float mx = -1e30f;
#pragma unroll
        for (int j = 0; j < 32; ++j) {
            int k = lane + j * 32;
            // faithful to source: NEG_MASK_SCALE = -1e-09
            float s = sc[k] + (-1e-9f) * (1.0f - (float)mrow[k]);
            vals[j] = s;
            mx = fmaxf(mx, s);
        }
#pragma unroll
        for (int o = 16; o; o >>= 1) mx = fmaxf(mx, __shfl_xor_sync(~0u, mx, o));
        float sum = 0.f;
#pragma unroll
        for (int j = 0; j < 32; ++j) { float e = __expf(vals[j] - mx); vals[j] = e; sum += e; }
#pragma unroll
        for (int o = 16; o; o >>= 1) sum += __shfl_xor_sync(~0u, sum, o);
        float inv = 1.0f / sum;
        float* aw = out_aw + (size_t)(b * QQ + q0 + warp) * KK;
#pragma unroll
        for (int j = 0; j < 32; ++j) {
            int k = lane + j * 32;
            float w = vals[j] * inv;
            sc[k] = w;
            aw[k] = w;
        }
    }
    __syncthreads();

    // ---- context: thread h = tid&127, handles 4 queries; value row reused across q
    {
        const int h = tid & 127;
        const int qg = tid >> 7;   // 0 or 1
        const float* vb = value + (size_t)b * KK * HH + h;
        const float* w0 = s_sc + (qg * 4 + 0) * KK;
        const float* w1 = s_sc + (qg * 4 + 1) * KK;
        const float* w2 = s_sc + (qg * 4 + 2) * KK;
        const float* w3 = s_sc + (qg * 4 + 3) * KK;
        float a0 = 0.f, a1 = 0.f, a2 = 0.f, a3 = 0.f;
#pragma unroll 8
        for (int k = 0; k < KK; ++k) {
            float v = vb[(size_t)k * HH];
            a0 += w0[k] * v;
            a1 += w1[k] * v;
            a2 += w2[k] * v;
            a3 += w3[k] * v;
        }
        float* ctx = out_ctx + (size_t)(b * QQ + q0 + qg * 4) * HH + h;
        ctx[0 * HH] = a0;
        ctx[1 * HH] = a1;
        ctx[2 * HH] = a2;
        ctx[3 * HH] = a3;
    }
}

extern "C" void kernel_launch(void* const* d_in, const int* in_sizes, int n_in,
                              void* d_out, int out_size) {
    // metadata order: query, key, value, mask, Wq, Wk, v
    const float* query = (const float*)d_in[0];
    const float* key   = (const float*)d_in[1];
    const float* value = (const float*)d_in[2];
    const int*   mask  = (const int*)d_in[3];
    const float* Wq    = (const float*)d_in[4];
    const float* Wk    = (const float*)d_in[5];
    const float* vvec  = (const float*)d_in[6];

    float* out_aw  = (float*)d_out;                          // (B,Q,K)
    float* out_ctx = out_aw + (size_t)BB * QQ * KK;          // (B,Q,H)

    const int smem_bytes = (2 * TILE * P4 * 4 + QT * KK) * (int)sizeof(float);
    static bool attr_set = false;
    if (!attr_set) {
        cudaFuncSetAttribute(attn_kernel, cudaFuncAttributeMaxDynamicSharedMemorySize, smem_bytes);
        attr_set = true;
    }

    proj_kernel<<<160, 256>>>(query, key, Wq, Wk);
    attn_kernel<<<BB * (QQ / QT), 256, smem_bytes>>>(value, mask, vvec, out_aw, out_ctx);
}

// round 4
// speedup vs baseline: 2.1124x; 1.0588x over previous
#include <cuda_runtime.h>
#include <cuda_bf16.h>
#include <cstdint>

// Problem constants (B=4, Q=256, K=1024, H=128)
#define BB 4
#define QQ 256
#define KK 1024
#define HH 128
#define QT 4            // queries per block
#define TILE 64         // k-rows per shared tile
#define P4 33           // float4 pitch of kp tile row (132 floats)

// Scratch for projections (device globals — no allocation allowed)
__device__ float g_qp[BB * QQ * HH];   // 512 KB
__device__ float g_kp[BB * KK * HH];   // 2 MB

__device__ __forceinline__ float fast_tanh(float x) {
    float y;
    asm("tanh.approx.f32 %0, %1;" : "=f"(y) : "f"(x));
    return y;
}

__device__ __forceinline__ void cp_async16(void* dst, const void* src) {
    uint32_t d = (uint32_t)__cvta_generic_to_shared(dst);
    asm volatile("cp.async.ca.shared.global [%0], [%1], 16;\n" :: "r"(d), "l"(src));
}

// ---------------- Fused projection GEMM: out[row][h] = sum_d in[row][d] * W[h][d]
// 64x64 tile per block, 256 threads (16x16), 4x4 register tile (stride-16 spread).
// blocks 0..31  : q-proj (1024 rows), blocks 32..159 : k-proj (4096 rows)
__global__ __launch_bounds__(256) void proj_kernel(
    const float* __restrict__ query, const float* __restrict__ key,
    const float* __restrict__ Wq, const float* __restrict__ Wk) {
    __shared__ float s_a[64 * 36];
    __shared__ float s_b[64 * 36];

    int bx = blockIdx.x;
    const float* in; const float* W; float* out;
    int rowTile, hTile;
    if (bx < 32) { in = query; W = Wq; out = g_qp; rowTile = (bx >> 1) * 64; hTile = (bx & 1) * 64; }
    else { bx -= 32; in = key; W = Wk; out = g_kp; rowTile = (bx >> 1) * 64; hTile = (bx & 1) * 64; }

    const int tid = threadIdx.x;
    const int tx = tid & 15;
    const int ty = tid >> 4;

    float acc[4][4] = {};

    for (int kc = 0; kc < 4; ++kc) {
        __syncthreads();
        {
            int idx = tid;
#pragma unroll
            for (int i = 0; i < 2; ++i, idx += 256) {
                int r = idx >> 3, c = idx & 7;
                float4 va = ((const float4*)(in + (size_t)(rowTile + r) * HH + kc * 32))[c];
                ((float4*)s_a)[r * 9 + c] = va;
                float4 vb = ((const float4*)(W + (size_t)(hTile + r) * HH + kc * 32))[c];
                ((float4*)s_b)[r * 9 + c] = vb;
            }
        }
        __syncthreads();

#pragma unroll
        for (int s = 0; s < 8; ++s) {
            float4 a[4], b[4];
#pragma unroll
            for (int i = 0; i < 4; ++i) a[i] = ((const float4*)s_a)[(ty + 16 * i) * 9 + s];
#pragma unroll
            for (int j = 0; j < 4; ++j) b[j] = ((const float4*)s_b)[(tx + 16 * j) * 9 + s];
#pragma unroll
            for (int i = 0; i < 4; ++i)
#pragma unroll
                for (int j = 0; j < 4; ++j)
                    acc[i][j] += a[i].x * b[j].x + a[i].y * b[j].y
                               + a[i].z * b[j].z + a[i].w * b[j].w;
        }
    }

#pragma unroll
    for (int i = 0; i < 4; ++i)
#pragma unroll
        for (int j = 0; j < 4; ++j)
            out[(size_t)(rowTile + ty + 16 * i) * HH + hTile + tx + 16 * j] = acc[i][j];
}

// ---------------- Fused attention: one block per (b, 4-query tile), 256 threads.
// Warp w: query q = w&3, k-half kh = w>>2 (kk in [kh*32, kh*32+32) of each tile).
// Thread: hs = lane>>3 (h-slice of 32), ksub = lane&7.
__global__ __launch_bounds__(256, 2) void attn_kernel(const float* __restrict__ value,
                                                      const int* __restrict__ mask,
                                                      const float* __restrict__ vvec,
                                                      float* __restrict__ out_aw,
                                                      float* __restrict__ out_ctx) {
    extern __shared__ float sm[];
    float4* s_kp = (float4*)sm;              // [2][TILE][P4] float4
    float*  s_sc = sm + 2 * TILE * P4 * 4;   // [QT][KK]
    float*  s_red = s_sc + QT * KK;          // [16]

    const int tid = threadIdx.x;
    const int bx = blockIdx.x;
    const int b = bx >> 6;
    const int q0 = (bx & 63) * QT;
    const int warp = tid >> 5;
    const int q = warp & 3;
    const int kh = warp >> 2;                // 0 or 1
    const int lane = tid & 31;
    const int hs = lane >> 3;
    const int ksub = lane & 7;

    const float4* kp4 = (const float4*)g_kp + (size_t)b * KK * (HH / 4);

    // per-thread register operands: q-projection slice and v slice (32 floats each)
    float4 qq[8], vv[8];
    {
        const float4* qp = (const float4*)g_qp + (size_t)(b * QQ + q0 + q) * (HH / 4) + hs * 8;
        const float4* v4 = (const float4*)vvec + hs * 8;
#pragma unroll
        for (int i = 0; i < 8; ++i) { qq[i] = qp[i]; vv[i] = v4[i]; }
    }

    auto stage = [&](int t, int buf) {
        const float4* src = kp4 + (size_t)t * TILE * (HH / 4);
        float4* dst = s_kp + buf * (TILE * P4);
#pragma unroll
        for (int i = 0; i < 8; ++i) {
            int idx = tid + i * 256;              // 0..2047
            int r = idx >> 5, c = idx & 31;
            cp_async16(dst + r * P4 + c, src + idx);
        }
        asm volatile("cp.async.commit_group;\n");
    };

    stage(0, 0);
    for (int t = 0; t < KK / TILE; ++t) {
        const int buf = t & 1;
        if (t < KK / TILE - 1) {
            stage(t + 1, buf ^ 1);
            asm volatile("cp.async.wait_group 1;\n");
        } else {
            asm volatile("cp.async.wait_group 0;\n");
        }
        __syncthreads();

        const float4* base = s_kp + buf * (TILE * P4) + hs * 8;
#pragma unroll
        for (int it = 0; it < 4; ++it) {
            const int kk = kh * 32 + ksub + it * 8;
            const float4* kr = base + kk * P4;
            float a0 = 0.f, a1 = 0.f;
#pragma unroll
            for (int i = 0; i < 8; i += 2) {
                float4 k0 = kr[i], k1 = kr[i + 1];
                a0 += vv[i].x * fast_tanh(qq[i].x + k0.x);
                a0 += vv[i].y * fast_tanh(qq[i].y + k0.y);
                a0 += vv[i].z * fast_tanh(qq[i].z + k0.z);
                a0 += vv[i].w * fast_tanh(qq[i].w + k0.w);
                a1 += vv[i + 1].x * fast_tanh(qq[i + 1].x + k1.x);
                a1 += vv[i + 1].y * fast_tanh(qq[i + 1].y + k1.y);
                a1 += vv[i + 1].z * fast_tanh(qq[i + 1].z + k1.z);
                a1 += vv[i + 1].w * fast_tanh(qq[i + 1].w + k1.w);
            }
            float acc = a0 + a1;
            acc += __shfl_xor_sync(~0u, acc, 8);
            acc += __shfl_xor_sync(~0u, acc, 16);
            if (hs == 0) s_sc[q * KK + t * TILE + kk] = acc;
        }
        __syncthreads();   // buffer `buf` is restaged next iteration
    }

    // ---- softmax: warp pair (q, kh) covers query q; lane holds k = 64t + 32kh + lane
    {
        float* sc = s_sc + q * KK;
        const int* mrow = mask + (size_t)(b * QQ + q0 + q) * KK;
        float vals[16];
        float mx = -1e30f;
#pragma unroll
        for (int t = 0; t < 16; ++t) {
            int k = t * 64 + kh * 32 + lane;
            // faithful to source: NEG_MASK_SCALE = -1e-09
            float s = sc[k] + (-1e-9f) * (1.0f - (float)mrow[k]);
            vals[t] = s;
            mx = fmaxf(mx, s);
        }
#pragma unroll
        for (int o = 16; o; o >>= 1) mx = fmaxf(mx, __shfl_xor_sync(~0u, mx, o));
        if (lane == 0) s_red[warp] = mx;
        __syncthreads();
        mx = fmaxf(s_red[q], s_red[4 + q]);

        float sum = 0.f;
#pragma unroll
        for (int t = 0; t < 16; ++t) { float e = __expf(vals[t] - mx); vals[t] = e; sum += e; }
#pragma unroll
        for (int o = 16; o; o >>= 1) sum += __shfl_xor_sync(~0u, sum, o);
        if (lane == 0) s_red[8 + warp] = sum;
        __syncthreads();
        float inv = 1.0f / (s_red[8 + q] + s_red[12 + q]);

        float* aw = out_aw + (size_t)(b * QQ + q0 + q) * KK;
#pragma unroll
        for (int t = 0; t < 16; ++t) {
            int k = t * 64 + kh * 32 + lane;
            float w = vals[t] * inv;
            sc[k] = w;
            aw[k] = w;
        }
    }
    __syncthreads();

    // ---- context: thread h = tid&127 handles 2 queries; value row reused across q
    {
        const int h = tid & 127;
        const int qg = tid >> 7;   // 0 or 1
        const float* vb = value + (size_t)b * KK * HH + h;
        const float* w0 = s_sc + (qg * 2 + 0) * KK;
        const float* w1 = s_sc + (qg * 2 + 1) * KK;
        float a0 = 0.f, a1 = 0.f;
#pragma unroll 8
        for (int k = 0; k < KK; ++k) {
            float v = vb[(size_t)k * HH];
            a0 += w0[k] * v;
            a1 += w1[k] * v;
        }
        float* ctx = out_ctx + (size_t)(b * QQ + q0 + qg * 2) * HH + h;
        ctx[0 * HH] = a0;
        ctx[1 * HH] = a1;
    }
}

extern "C" void kernel_launch(void* const* d_in, const int* in_sizes, int n_in,
                              void* d_out, int out_size) {
    // metadata order: query, key, value, mask, Wq, Wk, v
    const float* query = (const float*)d_in[0];
    const float* key   = (const float*)d_in[1];
    const float* value = (const float*)d_in[2];
    const int*   mask  = (const int*)d_in[3];
    const float* Wq    = (const float*)d_in[4];
    const float* Wk    = (const float*)d_in[5];
    const float* vvec  = (const float*)d_in[6];

    float* out_aw  = (float*)d_out;                          // (B,Q,K)
    float* out_ctx = out_aw + (size_t)BB * QQ * KK;          // (B,Q,H)

    const int smem_bytes = (2 * TILE * P4 * 4 + QT * KK + 16) * (int)sizeof(float);
    static bool attr_set = false;
    if (!attr_set) {
        cudaFuncSetAttribute(attn_kernel, cudaFuncAttributeMaxDynamicSharedMemorySize, smem_bytes);
        attr_set = true;
    }

    proj_kernel<<<160, 256>>>(query, key, Wq, Wk);
    attn_kernel<<<BB * (QQ / QT), 256, smem_bytes>>>(value, mask, vvec, out_aw, out_ctx);
}